// round 13
// baseline (speedup 1.0000x reference)
#include <cuda_runtime.h>
#include <cuda_bf16.h>
#include <cstdint>

// QuantumConvLayer: out[b, 2j]   = cos(q[2j]) * cos(pi * x[b, 2j])
//                   out[b, 2j+1] = out[b, 2j] * cos(q[2j+1] + pi * x[b, 2j+1])
// B = 4194304, N_QUBITS = 16. Streaming elementwise map at the LTS/HBM floor.
//
// Round 13: pure 256-bit memory ops (LDG.E.256 / STG.E.256), NO evict-last
// pinning (that was R11's regression suspect). Same 64B/thread footprint as
// the best-measured R2 shape: 2 front-batched 32B loads per thread, 2x 32B
// stores. Halves LSU issue slots / L1 wavefront bookkeeping per byte.

#define QCONV_THREADS 256
#define QCONV_UNROLL  2                                  // 32B chunks per thread
#define QCONV_TILE_C  (QCONV_THREADS * QCONV_UNROLL)     // 512 chunks = 1024 float4

__device__ __forceinline__ void ldg256(const float4* p, float4& a, float4& b)
{
    unsigned long long r0, r1, r2, r3;
    asm volatile("ld.global.nc.v4.b64 {%0,%1,%2,%3}, [%4];"
                 : "=l"(r0), "=l"(r1), "=l"(r2), "=l"(r3)
                 : "l"(p));
    a.x = __uint_as_float((unsigned)r0);  a.y = __uint_as_float((unsigned)(r0 >> 32));
    a.z = __uint_as_float((unsigned)r1);  a.w = __uint_as_float((unsigned)(r1 >> 32));
    b.x = __uint_as_float((unsigned)r2);  b.y = __uint_as_float((unsigned)(r2 >> 32));
    b.z = __uint_as_float((unsigned)r3);  b.w = __uint_as_float((unsigned)(r3 >> 32));
}

__device__ __forceinline__ void stg256(float4* p, const float4 a, const float4 b)
{
    unsigned long long r0 = (unsigned long long)__float_as_uint(a.x)
                          | ((unsigned long long)__float_as_uint(a.y) << 32);
    unsigned long long r1 = (unsigned long long)__float_as_uint(a.z)
                          | ((unsigned long long)__float_as_uint(a.w) << 32);
    unsigned long long r2 = (unsigned long long)__float_as_uint(b.x)
                          | ((unsigned long long)__float_as_uint(b.y) << 32);
    unsigned long long r3 = (unsigned long long)__float_as_uint(b.z)
                          | ((unsigned long long)__float_as_uint(b.w) << 32);
    asm volatile("st.global.cs.v4.b64 [%0], {%1,%2,%3,%4};"
                 :: "l"(p), "l"(r0), "l"(r1), "l"(r2), "l"(r3) : "memory");
}

__device__ __forceinline__ float4 qconv_compute(
    const float4 xv, float ce0, float ce1, float qo0, float qo1)
{
    const float PI = 3.14159265358979323846f;
    float z0 = ce0 * __cosf(PI * xv.x);
    float o0 = z0 * __cosf(qo0 + PI * xv.y);
    float z1 = ce1 * __cosf(PI * xv.z);
    float o1 = z1 * __cosf(qo1 + PI * xv.w);
    return make_float4(z0, o0, z1, o1);
}

__global__ __launch_bounds__(QCONV_THREADS) void qconv_kernel(
    const float4* __restrict__ x4,
    const float4* __restrict__ q4,   // q_params viewed as 4x float4
    float4* __restrict__ out4,
    int n_chunks)                    // n4 / 2
{
    int base = blockIdx.x * QCONV_TILE_C + threadIdx.x;   // 32B-chunk index

    // chunk c covers float4 indices 2c, 2c+1; (2c)&3 = 2*(c&1), invariant
    // across the unroll (stride 256 is even).
    int qe = 2 * (base & 1);
    float4 qva = q4[qe];
    float4 qvb = q4[qe + 1];
    float cea0 = __cosf(qva.x), cea1 = __cosf(qva.z);
    float ceb0 = __cosf(qvb.x), ceb1 = __cosf(qvb.z);

    // Front-batch 2 independent 32B loads per thread
    float4 xa[QCONV_UNROLL], xb[QCONV_UNROLL];
    bool ok[QCONV_UNROLL];
#pragma unroll
    for (int k = 0; k < QCONV_UNROLL; k++) {
        int c = base + k * QCONV_THREADS;
        ok[k] = (c < n_chunks);
        if (ok[k]) ldg256(x4 + 2 * (size_t)c, xa[k], xb[k]);
        else       xa[k] = xb[k] = make_float4(0.f, 0.f, 0.f, 0.f);
    }

#pragma unroll
    for (int k = 0; k < QCONV_UNROLL; k++) {
        float4 ra = qconv_compute(xa[k], cea0, cea1, qva.y, qva.w);
        float4 rb = qconv_compute(xb[k], ceb0, ceb1, qvb.y, qvb.w);
        int c = base + k * QCONV_THREADS;
        if (ok[k]) stg256(out4 + 2 * (size_t)c, ra, rb);
    }
}

extern "C" void kernel_launch(void* const* d_in, const int* in_sizes, int n_in,
                              void* d_out, int out_size)
{
    const float4* x4 = (const float4*)d_in[0];      // x: [B, 16] float32
    const float4* q4 = (const float4*)d_in[1];      // q_params: [16] float32
    float4* out4 = (float4*)d_out;

    int n4 = out_size / 4;                           // 16,777,216
    int n_chunks = n4 / 2;                           // 8,388,608
    int blocks = (n_chunks + QCONV_TILE_C - 1) / QCONV_TILE_C;  // 16,384

    qconv_kernel<<<blocks, QCONV_THREADS>>>(x4, q4, out4, n_chunks);
}